// round 1
// baseline (speedup 1.0000x reference)
#include <cuda_runtime.h>
#include <math.h>

#define BB 8
#define TT 8192
#define DD 128
#define KD 64
#define CL 256
#define NCHUNK (TT / CL)       // 32
#define NGROUP 4
#define GLEN (CL / NGROUP)     // 64
#define NTHREADS 256
#define SUBT 64

// ---------------- device globals (no allocation allowed) ----------------
__device__ float g_Wt[DD * KD];     // W_sn transposed: [d][k]
__device__ float g_a0[KD];
__device__ float g_w0[KD];
__device__ float g_bias[KD];

__device__ float g_aggL[BB * NCHUNK * KD * 4];  // local  (Zr,Zi,Ur,Ui)
__device__ float g_aggI[BB * NCHUNK * KD * 4];  // inclusive
__device__ int   g_flag[BB * NCHUNK];

// ---------------- helpers ----------------
__device__ __forceinline__ float softplusf(float x) {
    return (x > 20.0f) ? x : log1pf(expf(x));
}

__device__ __forceinline__ void zval(float am, float om_, float tm, float dtv,
                                     float a0k, float w0k, float& rc, float& rs) {
    float sc  = __expf(tm);
    float al  = a0k * __expf(am) * sc;
    float om  = w0k * __expf(om_) * sc;
    float rho = __expf(-al * dtv);
    float st, ct;
    __sincosf(om * dtv, &st, &ct);
    rc = rho * ct;
    rs = rho * st;
}

// ---------------- reset (flags) ----------------
__global__ void reset_kernel() {
    int i = threadIdx.x;
    if (i < BB * NCHUNK) g_flag[i] = 0;
}

// ---------------- prep: sigma via power iteration, W_sn^T, constants ----------------
__global__ void prep_kernel(const float* __restrict__ W, const float* __restrict__ bvec,
                            const float* __restrict__ s_real, const float* __restrict__ s_imag,
                            const float* __restrict__ tau_raw) {
    extern __shared__ float psm[];
    float* Ws = psm;               // 64 x 129 (padded)
    float* Gm = Ws + 64 * 129;     // 64 x 65  (padded)
    __shared__ float v[64], y[64], red[64], sig[1];

    int tid = threadIdx.x;

    for (int i = tid; i < KD * DD; i += NTHREADS) {
        int r = i / DD, c = i % DD;
        Ws[r * 129 + c] = W[i];
    }
    __syncthreads();

    // G = W W^T, 4x4 tile per thread
    {
        int i0 = (tid >> 4) * 4;
        int j0 = (tid & 15) * 4;
        float acc[4][4];
#pragma unroll
        for (int a = 0; a < 4; a++)
#pragma unroll
            for (int c = 0; c < 4; c++) acc[a][c] = 0.0f;
#pragma unroll 4
        for (int d = 0; d < DD; d++) {
            float wi[4], wj[4];
#pragma unroll
            for (int a = 0; a < 4; a++) wi[a] = Ws[(i0 + a) * 129 + d];
#pragma unroll
            for (int c = 0; c < 4; c++) wj[c] = Ws[(j0 + c) * 129 + d];
#pragma unroll
            for (int a = 0; a < 4; a++)
#pragma unroll
                for (int c = 0; c < 4; c++) acc[a][c] = fmaf(wi[a], wj[c], acc[a][c]);
        }
#pragma unroll
        for (int a = 0; a < 4; a++)
#pragma unroll
            for (int c = 0; c < 4; c++) Gm[(i0 + a) * 65 + (j0 + c)] = acc[a][c];
    }
    if (tid < 64) v[tid] = 1.0f + 0.001f * (float)tid;
    __syncthreads();

    // power iteration (normalize every 8 iters; lambda ~ 2.9 so no overflow)
    for (int it = 0; it < 160; it++) {
        if (tid < 64) {
            float s0 = 0, s1 = 0, s2 = 0, s3 = 0;
#pragma unroll 4
            for (int j = 0; j < 64; j += 4) {
                s0 = fmaf(Gm[tid * 65 + j + 0], v[j + 0], s0);
                s1 = fmaf(Gm[tid * 65 + j + 1], v[j + 1], s1);
                s2 = fmaf(Gm[tid * 65 + j + 2], v[j + 2], s2);
                s3 = fmaf(Gm[tid * 65 + j + 3], v[j + 3], s3);
            }
            y[tid] = (s0 + s1) + (s2 + s3);
        }
        __syncthreads();
        if ((it & 7) == 7) {
            if (tid < 64) red[tid] = y[tid] * y[tid];
            __syncthreads();
            for (int s = 32; s > 0; s >>= 1) {
                if (tid < s) red[tid] += red[tid + s];
                __syncthreads();
            }
            if (tid < 64) v[tid] = y[tid] * rsqrtf(red[0]);
        } else {
            if (tid < 64) v[tid] = y[tid];
        }
        __syncthreads();
    }

    // Rayleigh quotient: lambda = v^T G v (v normalized)
    if (tid < 64) {
        float s0 = 0, s1 = 0, s2 = 0, s3 = 0;
#pragma unroll 4
        for (int j = 0; j < 64; j += 4) {
            s0 = fmaf(Gm[tid * 65 + j + 0], v[j + 0], s0);
            s1 = fmaf(Gm[tid * 65 + j + 1], v[j + 1], s1);
            s2 = fmaf(Gm[tid * 65 + j + 2], v[j + 2], s2);
            s3 = fmaf(Gm[tid * 65 + j + 3], v[j + 3], s3);
        }
        red[tid] = v[tid] * ((s0 + s1) + (s2 + s3));
    }
    __syncthreads();
    for (int s = 32; s > 0; s >>= 1) {
        if (tid < s) red[tid] += red[tid + s];
        __syncthreads();
    }
    if (tid == 0) sig[0] = sqrtf(red[0]);
    __syncthreads();
    float inv = 1.0f / sig[0];

    // write W_sn transposed: g_Wt[d*64 + k] = W[k][d] / sigma
    for (int i = tid; i < DD * KD; i += NTHREADS) {
        int d = i / KD, k = i % KD;
        g_Wt[i] = Ws[k * 129 + d] * inv;
    }
    if (tid < 64) {
        float tau = softplusf(tau_raw[0]) + 1e-3f;
        g_a0[tid] = (softplusf(s_real[tid]) + 1e-6f) * tau;
        g_w0[tid] = s_imag[tid] * tau;
        g_bias[tid] = bvec[tid];
    }
}

// ---------------- main fused kernel: GEMM + compose + lookback + replay ----------------
__global__ void __launch_bounds__(NTHREADS, 1)
main_kernel(const float* __restrict__ x, const float* __restrict__ dtv_g,
            const float* __restrict__ amod, const float* __restrict__ omod,
            const float* __restrict__ tmod, float* __restrict__ out) {
    extern __shared__ float sm[];
    float* Wt_s = sm;                       // 8192
    float* xs   = Wt_s + DD * KD;           // 8192
    float* us   = xs + SUBT * DD;           // 16384
    float* agg  = us + CL * KD;             // NGROUP*KD*4 = 1024
    float* pre  = agg + NGROUP * KD * 4;    // 1024
    float* carry = pre + NGROUP * KD * 4;   // 128

    const int bid   = blockIdx.x;
    const int b     = bid % BB;
    const int chunk = bid / BB;
    const int tid   = threadIdx.x;
    const int t0    = chunk * CL;
    const int fidx  = b * NCHUNK + chunk;

    // load W_sn^T into smem
    {
        const float4* src = (const float4*)g_Wt;
        float4* dst = (float4*)Wt_s;
        for (int i = tid; i < DD * KD / 4; i += NTHREADS) dst[i] = src[i];
    }

    // ---------- phase 1: GEMM u = x @ Wsn^T + b  (4 subtiles of 64 t) ----------
    const int ty = tid >> 4;
    const int tx = tid & 15;
    float4 bv = *(const float4*)&g_bias[tx * 4];

    for (int sub = 0; sub < CL / SUBT; sub++) {
        __syncthreads();
        const float4* xsrc = (const float4*)(x + ((size_t)(b * TT + t0 + sub * SUBT)) * DD);
        float4* xd = (float4*)xs;
        for (int i = tid; i < SUBT * DD / 4; i += NTHREADS) xd[i] = xsrc[i];
        __syncthreads();

        float acc[4][4];
#pragma unroll
        for (int i = 0; i < 4; i++)
#pragma unroll
            for (int j = 0; j < 4; j++) acc[i][j] = 0.0f;

#pragma unroll 4
        for (int d = 0; d < DD; d += 4) {
            float4 w0 = *(const float4*)&Wt_s[(d + 0) * KD + tx * 4];
            float4 w1 = *(const float4*)&Wt_s[(d + 1) * KD + tx * 4];
            float4 w2 = *(const float4*)&Wt_s[(d + 2) * KD + tx * 4];
            float4 w3 = *(const float4*)&Wt_s[(d + 3) * KD + tx * 4];
#pragma unroll
            for (int i = 0; i < 4; i++) {
                float4 xv = *(const float4*)&xs[(ty * 4 + i) * DD + d];
                acc[i][0] = fmaf(xv.x, w0.x, acc[i][0]);
                acc[i][1] = fmaf(xv.x, w0.y, acc[i][1]);
                acc[i][2] = fmaf(xv.x, w0.z, acc[i][2]);
                acc[i][3] = fmaf(xv.x, w0.w, acc[i][3]);
                acc[i][0] = fmaf(xv.y, w1.x, acc[i][0]);
                acc[i][1] = fmaf(xv.y, w1.y, acc[i][1]);
                acc[i][2] = fmaf(xv.y, w1.z, acc[i][2]);
                acc[i][3] = fmaf(xv.y, w1.w, acc[i][3]);
                acc[i][0] = fmaf(xv.z, w2.x, acc[i][0]);
                acc[i][1] = fmaf(xv.z, w2.y, acc[i][1]);
                acc[i][2] = fmaf(xv.z, w2.z, acc[i][2]);
                acc[i][3] = fmaf(xv.z, w2.w, acc[i][3]);
                acc[i][0] = fmaf(xv.w, w3.x, acc[i][0]);
                acc[i][1] = fmaf(xv.w, w3.y, acc[i][1]);
                acc[i][2] = fmaf(xv.w, w3.z, acc[i][2]);
                acc[i][3] = fmaf(xv.w, w3.w, acc[i][3]);
            }
        }
#pragma unroll
        for (int i = 0; i < 4; i++) {
            float4 o;
            o.x = acc[i][0] + bv.x;
            o.y = acc[i][1] + bv.y;
            o.z = acc[i][2] + bv.z;
            o.w = acc[i][3] + bv.w;
            *(float4*)&us[(sub * SUBT + ty * 4 + i) * KD + tx * 4] = o;
        }
    }
    __syncthreads();

    // ---------- phase 2: compose (carry-free) ----------
    const int k = tid & 63;
    const int g = tid >> 6;
    const float a0k = g_a0[k];
    const float w0k = g_w0[k];

    const size_t base_bt = (size_t)b * TT + t0 + g * GLEN;
    const float* amp = amod + base_bt * KD + k;
    const float* omp_ = omod + base_bt * KD + k;
    const float* tmp_ = tmod + base_bt;
    const float* dtp = dtv_g + base_bt;

    float Zr = 1.0f, Zi = 0.0f, Ur = 0.0f, Ui = 0.0f;
#pragma unroll 4
    for (int i = 0; i < GLEN; i++) {
        float rc, rs;
        zval(amp[(size_t)i * KD], omp_[(size_t)i * KD], tmp_[i], dtp[i], a0k, w0k, rc, rs);
        float u = us[(g * GLEN + i) * KD + k];
        float Ur2 = fmaf(rc, Ur, fmaf(-rs, Ui, u));
        float Ui2 = fmaf(rc, Ui, rs * Ur);
        float Zr2 = fmaf(rc, Zr, -rs * Zi);
        float Zi2 = fmaf(rc, Zi, rs * Zr);
        Ur = Ur2; Ui = Ui2; Zr = Zr2; Zi = Zi2;
    }
    {
        float* a = &agg[(g * 64 + k) * 4];
        a[0] = Zr; a[1] = Zi; a[2] = Ur; a[3] = Ui;
    }
    __syncthreads();

    // ---------- phase 3: intra-block group scan + publish local aggregate ----------
    float bzr = 1.0f, bzi = 0.0f, bur = 0.0f, bui = 0.0f;  // block aggregate (tid<64)
    if (tid < 64) {
        float zr = 1.0f, zi = 0.0f, ur = 0.0f, ui = 0.0f;  // running exclusive prefix
#pragma unroll
        for (int gg = 0; gg < NGROUP; gg++) {
            float* p = &pre[(gg * 64 + k) * 4];
            p[0] = zr; p[1] = zi; p[2] = ur; p[3] = ui;
            float* a = &agg[(gg * 64 + k) * 4];
            float azr = a[0], azi = a[1], aur = a[2], aui = a[3];
            float nzr = azr * zr - azi * zi;
            float nzi = azr * zi + azi * zr;
            float nur = fmaf(azr, ur, fmaf(-azi, ui, aur));
            float nui = fmaf(azr, ui, fmaf(azi, ur, aui));
            zr = nzr; zi = nzi; ur = nur; ui = nui;
        }
        bzr = zr; bzi = zi; bur = ur; bui = ui;
        float* Lb = &g_aggL[((size_t)fidx * KD + k) * 4];
        Lb[0] = bzr; Lb[1] = bzi; Lb[2] = bur; Lb[3] = bui;
    }
    __syncthreads();
    if (tid == 0) {
        __threadfence();
        atomicExch(&g_flag[fidx], 1);
    }

    // ---------- phase 4: decoupled lookback ----------
    if (tid < 64) {
        float czr = 1.0f, czi = 0.0f, cur = 0.0f, cui = 0.0f;  // composite of chunks < chunk
        int p = chunk - 1;
        while (p >= 0) {
            int f;
            volatile int* vf = (volatile int*)&g_flag[b * NCHUNK + p];
            do { f = *vf; } while (f == 0);
            __threadfence();
            const float* src = (f == 2)
                ? &g_aggI[(((size_t)b * NCHUNK + p) * KD + k) * 4]
                : &g_aggL[(((size_t)b * NCHUNK + p) * KD + k) * 4];
            float azr = __ldcg(&src[0]);
            float azi = __ldcg(&src[1]);
            float aur = __ldcg(&src[2]);
            float aui = __ldcg(&src[3]);
            // A_p applied first, then current composite c
            float nzr = czr * azr - czi * azi;
            float nzi = czr * azi + czi * azr;
            float nur = fmaf(czr, aur, fmaf(-czi, aui, cur));
            float nui = fmaf(czr, aui, fmaf(czi, aur, cui));
            czr = nzr; czi = nzi; cur = nur; cui = nui;
            if (f == 2) break;
            p--;
        }
        carry[k] = cur;
        carry[64 + k] = cui;
        // inclusive = carry then block aggregate
        float izr = bzr * czr - bzi * czi;
        float izi = bzr * czi + bzi * czr;
        float iur = fmaf(bzr, cur, fmaf(-bzi, cui, bur));
        float iui = fmaf(bzr, cui, fmaf(bzi, cur, bui));
        float* Ib = &g_aggI[((size_t)fidx * KD + k) * 4];
        Ib[0] = izr; Ib[1] = izi; Ib[2] = iur; Ib[3] = iui;
    }
    __syncthreads();
    if (tid == 0) {
        __threadfence();
        atomicExch(&g_flag[fidx], 2);
    }

    // ---------- phase 5: replay with carry, write output ----------
    float pzr = pre[(g * 64 + k) * 4 + 0];
    float pzi = pre[(g * 64 + k) * 4 + 1];
    float pur = pre[(g * 64 + k) * 4 + 2];
    float pui = pre[(g * 64 + k) * 4 + 3];
    float chr_ = carry[k];
    float chi  = carry[64 + k];
    float hr = fmaf(pzr, chr_, fmaf(-pzi, chi, pur));
    float hi = fmaf(pzr, chi, fmaf(pzi, chr_, pui));

    float* outp = out + base_bt * (2 * KD);
#pragma unroll 4
    for (int i = 0; i < GLEN; i++) {
        float rc, rs;
        zval(amp[(size_t)i * KD], omp_[(size_t)i * KD], tmp_[i], dtp[i], a0k, w0k, rc, rs);
        float u = us[(g * GLEN + i) * KD + k];
        float hr2 = fmaf(rc, hr, fmaf(-rs, hi, u));
        float hi2 = fmaf(rc, hi, rs * hr);
        hr = hr2; hi = hi2;
        outp[(size_t)i * 128 + k]      = hr;
        outp[(size_t)i * 128 + 64 + k] = hi;
    }
}

// ---------------- launch ----------------
extern "C" void kernel_launch(void* const* d_in, const int* in_sizes, int n_in,
                              void* d_out, int out_size) {
    const float* x      = (const float*)d_in[0];
    const float* dt     = (const float*)d_in[1];
    const float* amod   = (const float*)d_in[2];
    const float* omod   = (const float*)d_in[3];
    const float* tmod   = (const float*)d_in[4];
    const float* s_real = (const float*)d_in[5];
    const float* s_imag = (const float*)d_in[6];
    const float* tau_r  = (const float*)d_in[7];
    const float* W      = (const float*)d_in[8];
    const float* bvec   = (const float*)d_in[9];
    float* out = (float*)d_out;

    static const size_t prep_smem = (64 * 129 + 64 * 65) * sizeof(float);
    static const size_t main_smem =
        (DD * KD + SUBT * DD + CL * KD + NGROUP * KD * 4 * 2 + 2 * KD) * sizeof(float);

    cudaFuncSetAttribute(prep_kernel, cudaFuncAttributeMaxDynamicSharedMemorySize, (int)prep_smem);
    cudaFuncSetAttribute(main_kernel, cudaFuncAttributeMaxDynamicSharedMemorySize, (int)main_smem);

    reset_kernel<<<1, NTHREADS>>>();
    prep_kernel<<<1, NTHREADS, prep_smem>>>(W, bvec, s_real, s_imag, tau_r);
    main_kernel<<<BB * NCHUNK, NTHREADS, main_smem>>>(x, dt, amod, omod, tmod, out);
}

// round 2
// speedup vs baseline: 2.0826x; 2.0826x over previous
#include <cuda_runtime.h>
#include <math.h>

#define BB 8
#define TT 8192
#define DD 128
#define KD 64
#define CL 256
#define NCHUNK (TT / CL)       // 32
#define NGROUP 4
#define GLEN (CL / NGROUP)     // 64
#define NTHREADS 256

// ---------------- device globals (no allocation allowed) ----------------
__device__ float g_Wt[DD * KD];     // W transposed (UNnormalized): [d][k]
__device__ float g_a0[KD];
__device__ float g_w0[KD];
__device__ float g_bias[KD];
__device__ float g_invs;            // 1/sigma

__device__ float g_aggL[BB * NCHUNK * KD * 4];  // local  (Zr,Zi,Ur,Ui)
__device__ float g_aggI[BB * NCHUNK * KD * 4];  // inclusive
__device__ int   g_flag[BB * NCHUNK];

// ---------------- helpers ----------------
__device__ __forceinline__ float softplusf(float x) {
    return (x > 20.0f) ? x : log1pf(expf(x));
}

__device__ __forceinline__ void zval(float am, float om_, float tm, float dtv,
                                     float a0k, float w0k, float& rc, float& rs) {
    float sc  = __expf(tm);
    float al  = a0k * __expf(am) * sc;
    float om  = w0k * __expf(om_) * sc;
    float rho = __expf(-al * dtv);
    float st, ct;
    __sincosf(om * dtv, &st, &ct);
    rc = rho * ct;
    rs = rho * st;
}

// packed f32x2 FMA (FFMA2) — ptxas never emits this from C++
__device__ __forceinline__ unsigned long long pk2(float v) {
    unsigned long long r;
    asm("mov.b64 %0, {%1, %1};" : "=l"(r) : "f"(v));
    return r;
}
__device__ __forceinline__ void fma2(unsigned long long& d,
                                     unsigned long long a, unsigned long long b) {
    asm("fma.rn.f32x2 %0, %1, %2, %0;" : "+l"(d) : "l"(a), "l"(b));
}

// ---------------- prep: flags reset + sigma (G^16 power) + constants ----------------
__global__ void prep_kernel(const float* __restrict__ W, const float* __restrict__ bvec,
                            const float* __restrict__ s_real, const float* __restrict__ s_imag,
                            const float* __restrict__ tau_raw) {
    extern __shared__ float psm[];
    float* Ws = psm;               // 64 x 129
    float* Gm = Ws + 64 * 129;     // 64 x 65
    float* Am = Gm + 64 * 65;      // 64 x 65
    float* Bm = Am + 64 * 65;      // 64 x 65
    __shared__ float v[64], y[64], red[64], sig[1];

    int tid = threadIdx.x;

    g_flag[tid] = 0;  // reset lookback flags (BB*NCHUNK == 256)

    for (int i = tid; i < KD * DD; i += NTHREADS) {
        int r = i / DD, c = i % DD;
        Ws[r * 129 + c] = W[i];
    }
    __syncthreads();

    const int i0 = (tid >> 4) * 4;
    const int j0 = (tid & 15) * 4;

    // G = W W^T (4x4 tile per thread)
    {
        float acc[4][4];
#pragma unroll
        for (int a = 0; a < 4; a++)
#pragma unroll
            for (int c = 0; c < 4; c++) acc[a][c] = 0.0f;
#pragma unroll 4
        for (int d = 0; d < DD; d++) {
            float wi[4], wj[4];
#pragma unroll
            for (int a = 0; a < 4; a++) wi[a] = Ws[(i0 + a) * 129 + d];
#pragma unroll
            for (int c = 0; c < 4; c++) wj[c] = Ws[(j0 + c) * 129 + d];
#pragma unroll
            for (int a = 0; a < 4; a++)
#pragma unroll
                for (int c = 0; c < 4; c++) acc[a][c] = fmaf(wi[a], wj[c], acc[a][c]);
        }
#pragma unroll
        for (int a = 0; a < 4; a++)
#pragma unroll
            for (int c = 0; c < 4; c++) Gm[(i0 + a) * 65 + (j0 + c)] = acc[a][c];
    }
    __syncthreads();

    // 4 repeated squarings: M = G^16 (symmetric, lambda^16 ~2.5e7 fits fp32)
    for (int sq = 0; sq < 4; sq++) {
        const float* src = (sq == 0) ? Gm : ((sq & 1) ? Am : Bm);
        float* dst = (sq & 1) ? Bm : Am;
        float acc[4][4];
#pragma unroll
        for (int a = 0; a < 4; a++)
#pragma unroll
            for (int c = 0; c < 4; c++) acc[a][c] = 0.0f;
#pragma unroll 4
        for (int l = 0; l < 64; l++) {
            float si[4], sj[4];
#pragma unroll
            for (int a = 0; a < 4; a++) si[a] = src[(i0 + a) * 65 + l];
#pragma unroll
            for (int c = 0; c < 4; c++) sj[c] = src[(j0 + c) * 65 + l];
#pragma unroll
            for (int a = 0; a < 4; a++)
#pragma unroll
                for (int c = 0; c < 4; c++) acc[a][c] = fmaf(si[a], sj[c], acc[a][c]);
        }
#pragma unroll
        for (int a = 0; a < 4; a++)
#pragma unroll
            for (int c = 0; c < 4; c++) dst[(i0 + a) * 65 + (j0 + c)] = acc[a][c];
        __syncthreads();
    }
    // M = Bm

    if (tid < 64) v[tid] = 1.0f + 0.001f * (float)tid;
    __syncthreads();

    // 8 power iterations on M = G^16 (normalize every iter)
    for (int it = 0; it < 8; it++) {
        if (tid < 64) {
            float s0 = 0, s1 = 0, s2 = 0, s3 = 0;
#pragma unroll 4
            for (int j = 0; j < 64; j += 4) {
                s0 = fmaf(Bm[tid * 65 + j + 0], v[j + 0], s0);
                s1 = fmaf(Bm[tid * 65 + j + 1], v[j + 1], s1);
                s2 = fmaf(Bm[tid * 65 + j + 2], v[j + 2], s2);
                s3 = fmaf(Bm[tid * 65 + j + 3], v[j + 3], s3);
            }
            y[tid] = (s0 + s1) + (s2 + s3);
        }
        __syncthreads();
        if (tid < 64) red[tid] = y[tid] * y[tid];
        __syncthreads();
        for (int s = 32; s > 0; s >>= 1) {
            if (tid < s) red[tid] += red[tid + s];
            __syncthreads();
        }
        if (tid < 64) v[tid] = y[tid] * rsqrtf(red[0]);
        __syncthreads();
    }

    // Rayleigh quotient on ORIGINAL G
    if (tid < 64) {
        float s0 = 0, s1 = 0, s2 = 0, s3 = 0;
#pragma unroll 4
        for (int j = 0; j < 64; j += 4) {
            s0 = fmaf(Gm[tid * 65 + j + 0], v[j + 0], s0);
            s1 = fmaf(Gm[tid * 65 + j + 1], v[j + 1], s1);
            s2 = fmaf(Gm[tid * 65 + j + 2], v[j + 2], s2);
            s3 = fmaf(Gm[tid * 65 + j + 3], v[j + 3], s3);
        }
        red[tid] = v[tid] * ((s0 + s1) + (s2 + s3));
    }
    __syncthreads();
    for (int s = 32; s > 0; s >>= 1) {
        if (tid < s) red[tid] += red[tid + s];
        __syncthreads();
    }
    if (tid == 0) {
        sig[0] = sqrtf(red[0]);
        g_invs = 1.0f / sig[0];
    }
    __syncthreads();

    // W transposed, UNnormalized (invs applied later on u)
    for (int i = tid; i < DD * KD; i += NTHREADS) {
        int d = i / KD, k = i % KD;
        g_Wt[i] = Ws[k * 129 + d];
    }
    if (tid < 64) {
        float tau = softplusf(tau_raw[0]) + 1e-3f;
        g_a0[tid] = (softplusf(s_real[tid]) + 1e-6f) * tau;
        g_w0[tid] = s_imag[tid] * tau;
        g_bias[tid] = bvec[tid];
    }
}

// ---------------- main fused kernel: FFMA2 GEMM + compose + lookback + replay ----------------
__global__ void __launch_bounds__(NTHREADS, 1)
main_kernel(const float* __restrict__ x, const float* __restrict__ dtv_g,
            const float* __restrict__ amod, const float* __restrict__ omod,
            const float* __restrict__ tmod, float* __restrict__ out) {
    extern __shared__ float sm[];
    float* Wt_s = sm;                       // 8192 floats
    float* xs   = Wt_s + DD * KD;           // 256 x 36 = 9216 floats
    float* us   = xs + 256 * 36;            // 16384 floats
    float* agg  = us + CL * KD;             // 1024
    float* pre  = agg + NGROUP * KD * 4;    // 1024
    float* carry = pre + NGROUP * KD * 4;   // 128

    const int bid   = blockIdx.x;
    const int b     = bid % BB;
    const int chunk = bid / BB;
    const int tid   = threadIdx.x;
    const int t0    = chunk * CL;
    const int fidx  = b * NCHUNK + chunk;

    // load W^T (unnormalized) into smem
    {
        const float4* src = (const float4*)g_Wt;
        float4* dst = (float4*)Wt_s;
        for (int i = tid; i < DD * KD / 4; i += NTHREADS) dst[i] = src[i];
    }

    // ---------- phase 1: raw = x @ W^T via FFMA2, 8t x 8k register tiles ----------
    const int ty = tid >> 3;   // 0..31 : 8 consecutive t rows each
    const int tx = tid & 7;    // 0..7  : 8 consecutive k cols each

    unsigned long long acc[8][4];
#pragma unroll
    for (int i = 0; i < 8; i++)
#pragma unroll
        for (int p = 0; p < 4; p++) acc[i][p] = 0ull;

    const float* xg_base = x + ((size_t)b * TT + t0) * DD;

    for (int dc = 0; dc < 4; dc++) {          // d chunks of 32
        __syncthreads();
        {
            const float* xg = xg_base + dc * 32;
#pragma unroll
            for (int i = tid; i < 256 * 8; i += NTHREADS) {
                int row = i >> 3, q = i & 7;
                *(float4*)&xs[row * 36 + q * 4] = *(const float4*)&xg[(size_t)row * DD + q * 4];
            }
        }
        __syncthreads();

#pragma unroll 1
        for (int d4 = 0; d4 < 8; d4++) {      // 4 d per step
            float4 xv[8];
#pragma unroll
            for (int i = 0; i < 8; i++)
                xv[i] = *(const float4*)&xs[(ty * 8 + i) * 36 + d4 * 4];
            unsigned long long wv[4][4];
#pragma unroll
            for (int dd = 0; dd < 4; dd++) {
                const unsigned long long* wp =
                    (const unsigned long long*)&Wt_s[(dc * 32 + d4 * 4 + dd) * KD + tx * 8];
#pragma unroll
                for (int p = 0; p < 4; p++) wv[dd][p] = wp[p];
            }
#pragma unroll
            for (int i = 0; i < 8; i++) {
                float xf0 = xv[i].x, xf1 = xv[i].y, xf2 = xv[i].z, xf3 = xv[i].w;
                unsigned long long xx;
                xx = pk2(xf0);
#pragma unroll
                for (int p = 0; p < 4; p++) fma2(acc[i][p], xx, wv[0][p]);
                xx = pk2(xf1);
#pragma unroll
                for (int p = 0; p < 4; p++) fma2(acc[i][p], xx, wv[1][p]);
                xx = pk2(xf2);
#pragma unroll
                for (int p = 0; p < 4; p++) fma2(acc[i][p], xx, wv[2][p]);
                xx = pk2(xf3);
#pragma unroll
                for (int p = 0; p < 4; p++) fma2(acc[i][p], xx, wv[3][p]);
            }
        }
    }
    // store raw u (unscaled) to smem
#pragma unroll
    for (int i = 0; i < 8; i++) {
        unsigned long long* up = (unsigned long long*)&us[(ty * 8 + i) * KD + tx * 8];
#pragma unroll
        for (int p = 0; p < 4; p++) up[p] = acc[i][p];
    }
    __syncthreads();

    // ---------- phase 2: compose (carry-free) ----------
    const int k = tid & 63;
    const int g = tid >> 6;
    const float a0k = g_a0[k];
    const float w0k = g_w0[k];
    const float invs = g_invs;
    const float bk = g_bias[k];

    const size_t base_bt = (size_t)b * TT + t0 + g * GLEN;
    const float* amp = amod + base_bt * KD + k;
    const float* omp_ = omod + base_bt * KD + k;
    const float* tmp_ = tmod + base_bt;
    const float* dtp = dtv_g + base_bt;

    float Zr = 1.0f, Zi = 0.0f, Ur = 0.0f, Ui = 0.0f;
#pragma unroll 4
    for (int i = 0; i < GLEN; i++) {
        float rc, rs;
        zval(amp[(size_t)i * KD], omp_[(size_t)i * KD], tmp_[i], dtp[i], a0k, w0k, rc, rs);
        float u = fmaf(us[(g * GLEN + i) * KD + k], invs, bk);
        float Ur2 = fmaf(rc, Ur, fmaf(-rs, Ui, u));
        float Ui2 = fmaf(rc, Ui, rs * Ur);
        float Zr2 = fmaf(rc, Zr, -rs * Zi);
        float Zi2 = fmaf(rc, Zi, rs * Zr);
        Ur = Ur2; Ui = Ui2; Zr = Zr2; Zi = Zi2;
    }
    {
        float* a = &agg[(g * 64 + k) * 4];
        a[0] = Zr; a[1] = Zi; a[2] = Ur; a[3] = Ui;
    }
    __syncthreads();

    // ---------- phase 3: intra-block group scan + publish local aggregate ----------
    float bzr = 1.0f, bzi = 0.0f, bur = 0.0f, bui = 0.0f;
    if (tid < 64) {
        float zr = 1.0f, zi = 0.0f, ur = 0.0f, ui = 0.0f;
#pragma unroll
        for (int gg = 0; gg < NGROUP; gg++) {
            float* p = &pre[(gg * 64 + k) * 4];
            p[0] = zr; p[1] = zi; p[2] = ur; p[3] = ui;
            float* a = &agg[(gg * 64 + k) * 4];
            float azr = a[0], azi = a[1], aur = a[2], aui = a[3];
            float nzr = azr * zr - azi * zi;
            float nzi = azr * zi + azi * zr;
            float nur = fmaf(azr, ur, fmaf(-azi, ui, aur));
            float nui = fmaf(azr, ui, fmaf(azi, ur, aui));
            zr = nzr; zi = nzi; ur = nur; ui = nui;
        }
        bzr = zr; bzi = zi; bur = ur; bui = ui;
        float* Lb = &g_aggL[((size_t)fidx * KD + k) * 4];
        Lb[0] = bzr; Lb[1] = bzi; Lb[2] = bur; Lb[3] = bui;
    }
    __syncthreads();
    if (tid == 0) {
        __threadfence();
        atomicExch(&g_flag[fidx], 1);
    }

    // ---------- phase 4: decoupled lookback ----------
    if (tid < 64) {
        float czr = 1.0f, czi = 0.0f, cur = 0.0f, cui = 0.0f;
        int p = chunk - 1;
        while (p >= 0) {
            int f;
            volatile int* vf = (volatile int*)&g_flag[b * NCHUNK + p];
            do { f = *vf; } while (f == 0);
            __threadfence();
            const float* src = (f == 2)
                ? &g_aggI[(((size_t)b * NCHUNK + p) * KD + k) * 4]
                : &g_aggL[(((size_t)b * NCHUNK + p) * KD + k) * 4];
            float azr = __ldcg(&src[0]);
            float azi = __ldcg(&src[1]);
            float aur = __ldcg(&src[2]);
            float aui = __ldcg(&src[3]);
            float nzr = czr * azr - czi * azi;
            float nzi = czr * azi + czi * azr;
            float nur = fmaf(czr, aur, fmaf(-czi, aui, cur));
            float nui = fmaf(czr, aui, fmaf(czi, aur, cui));
            czr = nzr; czi = nzi; cur = nur; cui = nui;
            if (f == 2) break;
            p--;
        }
        carry[k] = cur;
        carry[64 + k] = cui;
        float izr = bzr * czr - bzi * czi;
        float izi = bzr * czi + bzi * czr;
        float iur = fmaf(bzr, cur, fmaf(-bzi, cui, bur));
        float iui = fmaf(bzr, cui, fmaf(bzi, cur, bui));
        float* Ib = &g_aggI[((size_t)fidx * KD + k) * 4];
        Ib[0] = izr; Ib[1] = izi; Ib[2] = iur; Ib[3] = iui;
    }
    __syncthreads();
    if (tid == 0) {
        __threadfence();
        atomicExch(&g_flag[fidx], 2);
    }

    // ---------- phase 5: replay with carry, write output ----------
    float pzr = pre[(g * 64 + k) * 4 + 0];
    float pzi = pre[(g * 64 + k) * 4 + 1];
    float pur = pre[(g * 64 + k) * 4 + 2];
    float pui = pre[(g * 64 + k) * 4 + 3];
    float chr_ = carry[k];
    float chi  = carry[64 + k];
    float hr = fmaf(pzr, chr_, fmaf(-pzi, chi, pur));
    float hi = fmaf(pzr, chi, fmaf(pzi, chr_, pui));

    float* outp = out + base_bt * (2 * KD);
#pragma unroll 4
    for (int i = 0; i < GLEN; i++) {
        float rc, rs;
        zval(amp[(size_t)i * KD], omp_[(size_t)i * KD], tmp_[i], dtp[i], a0k, w0k, rc, rs);
        float u = fmaf(us[(g * GLEN + i) * KD + k], invs, bk);
        float hr2 = fmaf(rc, hr, fmaf(-rs, hi, u));
        float hi2 = fmaf(rc, hi, rs * hr);
        hr = hr2; hi = hi2;
        outp[(size_t)i * 128 + k]      = hr;
        outp[(size_t)i * 128 + 64 + k] = hi;
    }
}

// ---------------- launch ----------------
extern "C" void kernel_launch(void* const* d_in, const int* in_sizes, int n_in,
                              void* d_out, int out_size) {
    const float* x      = (const float*)d_in[0];
    const float* dt     = (const float*)d_in[1];
    const float* amod   = (const float*)d_in[2];
    const float* omod   = (const float*)d_in[3];
    const float* tmod   = (const float*)d_in[4];
    const float* s_real = (const float*)d_in[5];
    const float* s_imag = (const float*)d_in[6];
    const float* tau_r  = (const float*)d_in[7];
    const float* W      = (const float*)d_in[8];
    const float* bvec   = (const float*)d_in[9];
    float* out = (float*)d_out;

    static const size_t prep_smem = (64 * 129 + 3 * 64 * 65) * sizeof(float);
    static const size_t main_smem =
        (DD * KD + 256 * 36 + CL * KD + NGROUP * KD * 4 * 2 + 2 * KD) * sizeof(float);

    cudaFuncSetAttribute(prep_kernel, cudaFuncAttributeMaxDynamicSharedMemorySize, (int)prep_smem);
    cudaFuncSetAttribute(main_kernel, cudaFuncAttributeMaxDynamicSharedMemorySize, (int)main_smem);

    prep_kernel<<<1, NTHREADS, prep_smem>>>(W, bvec, s_real, s_imag, tau_r);
    main_kernel<<<BB * NCHUNK, NTHREADS, main_smem>>>(x, dt, amod, omod, tmod, out);
}

// round 3
// speedup vs baseline: 2.9468x; 1.4150x over previous
#include <cuda_runtime.h>
#include <math.h>

#define BB 8
#define TT 8192
#define DD 128
#define KD 64
#define CL 256
#define NCHUNK (TT / CL)       // 32
#define NGROUP 4
#define GLEN (CL / NGROUP)     // 64
#define NTHREADS 256
#define NBLK (BB * NCHUNK)     // 256

typedef unsigned long long ull;

// ---------------- device globals (no allocation allowed) ----------------
__device__ float g_a0[KD];
__device__ float g_w0[KD];
__device__ float g_bias[KD];
__device__ float g_invs;

__device__ float g_aggL[NBLK * KD * 4];  // local  (Zr,Zi,Ur,Ui)
__device__ float g_aggI[NBLK * KD * 4];  // inclusive
__device__ int   g_flag[NBLK];
__device__ int   g_ready;
__device__ int   g_done;

// ---------------- helpers ----------------
__device__ __forceinline__ float softplusf(float x) {
    return (x > 20.0f) ? x : log1pf(expf(x));
}

__device__ __forceinline__ void zval(float am, float om_, float tm, float dtv,
                                     float a0k, float w0k, float& rc, float& rs) {
    float sc  = __expf(tm);
    float al  = a0k * __expf(am) * sc;
    float om  = w0k * __expf(om_) * sc;
    float rho = __expf(-al * dtv);
    float st, ct;
    __sincosf(om * dtv, &st, &ct);
    rc = rho * ct;
    rs = rho * st;
}

__device__ __forceinline__ ull pk2(float v) {
    ull r;
    asm("mov.b64 %0, {%1, %1};" : "=l"(r) : "f"(v));
    return r;
}
__device__ __forceinline__ void fma2(ull& d, ull a, ull b) {
    asm("fma.rn.f32x2 %0, %1, %2, %0;" : "+l"(d) : "l"(a), "l"(b));
}
__device__ __forceinline__ void upk(ull v, float& lo, float& hi) {
    asm("mov.b64 {%0, %1}, %2;" : "=f"(lo), "=f"(hi) : "l"(v));
}

// ---------------- prep (runs inside block 0 only) ----------------
__device__ void do_prep(float* sm, const float* __restrict__ W,
                        const float* __restrict__ bvec,
                        const float* __restrict__ s_real,
                        const float* __restrict__ s_imag,
                        const float* __restrict__ tau_raw, int tid) {
    // overlay on dynamic smem (dead before GEMM starts)
    float* WsT = sm;                 // 128 x 68
    float* Gm  = WsT + 128 * 68;     // 64 x 68
    float* Am  = Gm + 64 * 68;
    float* Bm  = Am + 64 * 68;
    float* pv  = Bm + 64 * 68;       // 64
    float* py  = pv + 64;
    float* pred = py + 64;

    // load W transposed into smem: WsT[d][k]
    for (int i = tid; i < 64 * 32; i += NTHREADS) {
        int k = i >> 5, q = i & 31;
        float4 w4 = *(const float4*)&W[k * DD + q * 4];
        WsT[(q * 4 + 0) * 68 + k] = w4.x;
        WsT[(q * 4 + 1) * 68 + k] = w4.y;
        WsT[(q * 4 + 2) * 68 + k] = w4.z;
        WsT[(q * 4 + 3) * 68 + k] = w4.w;
    }
    __syncthreads();

    const int i0 = (tid >> 4) * 4;
    const int j0 = (tid & 15) * 4;

    // G = W W^T via FFMA2 (4x4 tile per thread, k-pairs packed)
    {
        ull acc2[4][2];
#pragma unroll
        for (int a = 0; a < 4; a++) { acc2[a][0] = 0ull; acc2[a][1] = 0ull; }
        for (int d = 0; d < DD; d++) {
            float4 si = *(const float4*)&WsT[d * 68 + i0];
            ull sj0 = *(const ull*)&WsT[d * 68 + j0];
            ull sj1 = *(const ull*)&WsT[d * 68 + j0 + 2];
            ull xx;
            xx = pk2(si.x); fma2(acc2[0][0], xx, sj0); fma2(acc2[0][1], xx, sj1);
            xx = pk2(si.y); fma2(acc2[1][0], xx, sj0); fma2(acc2[1][1], xx, sj1);
            xx = pk2(si.z); fma2(acc2[2][0], xx, sj0); fma2(acc2[2][1], xx, sj1);
            xx = pk2(si.w); fma2(acc2[3][0], xx, sj0); fma2(acc2[3][1], xx, sj1);
        }
#pragma unroll
        for (int a = 0; a < 4; a++) {
            float lo, hi;
            upk(acc2[a][0], lo, hi);
            Gm[(i0 + a) * 68 + j0 + 0] = lo; Gm[(i0 + a) * 68 + j0 + 1] = hi;
            upk(acc2[a][1], lo, hi);
            Gm[(i0 + a) * 68 + j0 + 2] = lo; Gm[(i0 + a) * 68 + j0 + 3] = hi;
        }
    }
    __syncthreads();

    // 4 squarings: M = G^16. Matrices symmetric -> row access via transposed index.
    const float* srcs[4] = {Gm, Am, Bm, Am};
    float* dsts[4] = {Am, Bm, Am, Bm};
    for (int sq = 0; sq < 4; sq++) {
        const float* src = srcs[sq];
        float* dst = dsts[sq];
        ull acc2[4][2];
#pragma unroll
        for (int a = 0; a < 4; a++) { acc2[a][0] = 0ull; acc2[a][1] = 0ull; }
        for (int l = 0; l < 64; l++) {
            float4 si = *(const float4*)&src[l * 68 + i0];
            ull sj0 = *(const ull*)&src[l * 68 + j0];
            ull sj1 = *(const ull*)&src[l * 68 + j0 + 2];
            ull xx;
            xx = pk2(si.x); fma2(acc2[0][0], xx, sj0); fma2(acc2[0][1], xx, sj1);
            xx = pk2(si.y); fma2(acc2[1][0], xx, sj0); fma2(acc2[1][1], xx, sj1);
            xx = pk2(si.z); fma2(acc2[2][0], xx, sj0); fma2(acc2[2][1], xx, sj1);
            xx = pk2(si.w); fma2(acc2[3][0], xx, sj0); fma2(acc2[3][1], xx, sj1);
        }
        __syncthreads();
#pragma unroll
        for (int a = 0; a < 4; a++) {
            float lo, hi;
            upk(acc2[a][0], lo, hi);
            dst[(i0 + a) * 68 + j0 + 0] = lo; dst[(i0 + a) * 68 + j0 + 1] = hi;
            upk(acc2[a][1], lo, hi);
            dst[(i0 + a) * 68 + j0 + 2] = lo; dst[(i0 + a) * 68 + j0 + 3] = hi;
        }
        __syncthreads();
    }
    // M = Bm

    if (tid < 64) pv[tid] = 1.0f + 0.001f * (float)tid;
    __syncthreads();

    for (int it = 0; it < 8; it++) {
        if (tid < 64) {
            float s = 0.0f;
#pragma unroll 4
            for (int j = 0; j < 64; j += 4) {
                float4 m4 = *(const float4*)&Bm[tid * 68 + j];
                float4 v4 = *(const float4*)&pv[j];
                s = fmaf(m4.x, v4.x, s);
                s = fmaf(m4.y, v4.y, s);
                s = fmaf(m4.z, v4.z, s);
                s = fmaf(m4.w, v4.w, s);
            }
            py[tid] = s;
            pred[tid] = s * s;
        }
        __syncthreads();
        for (int s = 32; s > 0; s >>= 1) {
            if (tid < s) pred[tid] += pred[tid + s];
            __syncthreads();
        }
        if (tid < 64) pv[tid] = py[tid] * rsqrtf(pred[0]);
        __syncthreads();
    }

    // Rayleigh on original G
    if (tid < 64) {
        float s = 0.0f;
#pragma unroll 4
        for (int j = 0; j < 64; j += 4) {
            float4 m4 = *(const float4*)&Gm[tid * 68 + j];
            float4 v4 = *(const float4*)&pv[j];
            s = fmaf(m4.x, v4.x, s);
            s = fmaf(m4.y, v4.y, s);
            s = fmaf(m4.z, v4.z, s);
            s = fmaf(m4.w, v4.w, s);
        }
        pred[tid] = pv[tid] * s;
    }
    __syncthreads();
    for (int s = 32; s > 0; s >>= 1) {
        if (tid < s) pred[tid] += pred[tid + s];
        __syncthreads();
    }
    if (tid == 0) g_invs = 1.0f / sqrtf(pred[0]);
    if (tid < 64) {
        float tau = softplusf(tau_raw[0]) + 1e-3f;
        g_a0[tid] = (softplusf(s_real[tid]) + 1e-6f) * tau;
        g_w0[tid] = s_imag[tid] * tau;
        g_bias[tid] = bvec[tid];
    }
    __syncthreads();
    if (tid == 0) {
        __threadfence();
        atomicExch(&g_ready, 1);
    }
}

// ---------------- fused kernel ----------------
__global__ void __launch_bounds__(NTHREADS, 2)
main_kernel(const float* __restrict__ x, const float* __restrict__ dtv_g,
            const float* __restrict__ amod, const float* __restrict__ omod,
            const float* __restrict__ tmod, float* __restrict__ out,
            const float* __restrict__ W, const float* __restrict__ bvec,
            const float* __restrict__ s_real, const float* __restrict__ s_imag,
            const float* __restrict__ tau_raw) {
    extern __shared__ float sm[];
    float* us   = sm;                        // 16384
    float* xs   = us + CL * KD;              // 256 x 20 = 5120
    float* wc   = xs + 256 * 20;             // 16 x 64 = 1024
    float* agg  = wc + 16 * 64;              // 1024
    float* pre  = agg + NGROUP * KD * 4;     // 1024
    float* carry = pre + NGROUP * KD * 4;    // 128

    const int bid   = blockIdx.x;
    const int b     = bid % BB;
    const int chunk = bid / BB;
    const int tid   = threadIdx.x;
    const int t0    = chunk * CL;
    const int fidx  = b * NCHUNK + chunk;

    // ---------- block 0: prep (sigma, constants), others go straight to GEMM ----------
    if (bid == 0) {
        do_prep(sm, W, bvec, s_real, s_imag, tau_raw, tid);
        __syncthreads();
    }

    // ---------- phase 1: raw = x @ W^T via FFMA2, 8t x 8k regs, d chunks of 16 ----------
    const int ty = tid >> 3;   // 0..31 : 8 t rows each
    const int tx = tid & 7;    // 0..7  : 8 k cols each

    ull acc[8][4];
#pragma unroll
    for (int i = 0; i < 8; i++)
#pragma unroll
        for (int p = 0; p < 4; p++) acc[i][p] = 0ull;

    const float* xg_base = x + ((size_t)b * TT + t0) * DD;
    {
        const int kk = tid & 63;
        const int qq = tid >> 6;
        for (int dc = 0; dc < 8; dc++) {
            __syncthreads();
            // stage x chunk: 256 rows x 16 d
#pragma unroll
            for (int j = 0; j < 4; j++) {
                int f = tid + j * NTHREADS;
                int row = f >> 2, q = f & 3;
                *(float4*)&xs[row * 20 + q * 4] =
                    *(const float4*)&xg_base[(size_t)row * DD + dc * 16 + q * 4];
            }
            // stage W chunk transposed: wc[d][k]
            {
                float4 w4 = *(const float4*)&W[kk * DD + dc * 16 + qq * 4];
                wc[(qq * 4 + 0) * 64 + kk] = w4.x;
                wc[(qq * 4 + 1) * 64 + kk] = w4.y;
                wc[(qq * 4 + 2) * 64 + kk] = w4.z;
                wc[(qq * 4 + 3) * 64 + kk] = w4.w;
            }
            __syncthreads();

#pragma unroll
            for (int dd = 0; dd < 16; dd += 2) {
                ull w0[4], w1[4];
                const ull* wp0 = (const ull*)&wc[dd * 64 + tx * 8];
                const ull* wp1 = (const ull*)&wc[(dd + 1) * 64 + tx * 8];
#pragma unroll
                for (int p = 0; p < 4; p++) { w0[p] = wp0[p]; w1[p] = wp1[p]; }
#pragma unroll
                for (int i = 0; i < 8; i++) {
                    float2 xv = *(const float2*)&xs[(ty * 8 + i) * 20 + dd];
                    ull xx0 = pk2(xv.x);
#pragma unroll
                    for (int p = 0; p < 4; p++) fma2(acc[i][p], xx0, w0[p]);
                    ull xx1 = pk2(xv.y);
#pragma unroll
                    for (int p = 0; p < 4; p++) fma2(acc[i][p], xx1, w1[p]);
                }
            }
        }
    }
    __syncthreads();
#pragma unroll
    for (int i = 0; i < 8; i++) {
        ull* up = (ull*)&us[(ty * 8 + i) * KD + tx * 8];
#pragma unroll
        for (int p = 0; p < 4; p++) up[p] = acc[i][p];
    }

    // ---------- wait for prep ----------
    if (tid == 0) {
        volatile int* rp = &g_ready;
        while (*rp == 0) { }
    }
    __syncthreads();

    // ---------- phase 2: compose (carry-free) ----------
    const int k = tid & 63;
    const int g = tid >> 6;
    const float a0k = g_a0[k];
    const float w0k = g_w0[k];
    const float invs = g_invs;
    const float bk = g_bias[k];

    const size_t base_bt = (size_t)b * TT + t0 + g * GLEN;
    const float* amp = amod + base_bt * KD + k;
    const float* omp_ = omod + base_bt * KD + k;
    const float* tmp_ = tmod + base_bt;
    const float* dtp = dtv_g + base_bt;

    float Zr = 1.0f, Zi = 0.0f, Ur = 0.0f, Ui = 0.0f;
#pragma unroll 4
    for (int i = 0; i < GLEN; i++) {
        float rc, rs;
        zval(amp[(size_t)i * KD], omp_[(size_t)i * KD], tmp_[i], dtp[i], a0k, w0k, rc, rs);
        float u = fmaf(us[(g * GLEN + i) * KD + k], invs, bk);
        float Ur2 = fmaf(rc, Ur, fmaf(-rs, Ui, u));
        float Ui2 = fmaf(rc, Ui, rs * Ur);
        float Zr2 = fmaf(rc, Zr, -rs * Zi);
        float Zi2 = fmaf(rc, Zi, rs * Zr);
        Ur = Ur2; Ui = Ui2; Zr = Zr2; Zi = Zi2;
    }
    {
        float* a = &agg[(g * 64 + k) * 4];
        a[0] = Zr; a[1] = Zi; a[2] = Ur; a[3] = Ui;
    }
    __syncthreads();

    // ---------- phase 3: intra-block group scan + publish local aggregate ----------
    float bzr = 1.0f, bzi = 0.0f, bur = 0.0f, bui = 0.0f;
    if (tid < 64) {
        float zr = 1.0f, zi = 0.0f, ur = 0.0f, ui = 0.0f;
#pragma unroll
        for (int gg = 0; gg < NGROUP; gg++) {
            float* p = &pre[(gg * 64 + k) * 4];
            p[0] = zr; p[1] = zi; p[2] = ur; p[3] = ui;
            float* a = &agg[(gg * 64 + k) * 4];
            float azr = a[0], azi = a[1], aur = a[2], aui = a[3];
            float nzr = azr * zr - azi * zi;
            float nzi = azr * zi + azi * zr;
            float nur = fmaf(azr, ur, fmaf(-azi, ui, aur));
            float nui = fmaf(azr, ui, fmaf(azi, ur, aui));
            zr = nzr; zi = nzi; ur = nur; ui = nui;
        }
        bzr = zr; bzi = zi; bur = ur; bui = ui;
        float* Lb = &g_aggL[((size_t)fidx * KD + k) * 4];
        Lb[0] = bzr; Lb[1] = bzi; Lb[2] = bur; Lb[3] = bui;
    }
    __syncthreads();
    if (tid == 0) {
        __threadfence();
        atomicExch(&g_flag[fidx], 1);
    }

    // ---------- phase 4: decoupled lookback ----------
    if (tid < 64) {
        float czr = 1.0f, czi = 0.0f, cur = 0.0f, cui = 0.0f;
        int p = chunk - 1;
        while (p >= 0) {
            int f;
            volatile int* vf = (volatile int*)&g_flag[b * NCHUNK + p];
            do { f = *vf; } while (f == 0);
            __threadfence();
            const float* src = (f == 2)
                ? &g_aggI[(((size_t)b * NCHUNK + p) * KD + k) * 4]
                : &g_aggL[(((size_t)b * NCHUNK + p) * KD + k) * 4];
            float azr = __ldcg(&src[0]);
            float azi = __ldcg(&src[1]);
            float aur = __ldcg(&src[2]);
            float aui = __ldcg(&src[3]);
            float nzr = czr * azr - czi * azi;
            float nzi = czr * azi + czi * azr;
            float nur = fmaf(czr, aur, fmaf(-czi, aui, cur));
            float nui = fmaf(czr, aui, fmaf(czi, aur, cui));
            czr = nzr; czi = nzi; cur = nur; cui = nui;
            if (f == 2) break;
            p--;
        }
        carry[k] = cur;
        carry[64 + k] = cui;
        float izr = bzr * czr - bzi * czi;
        float izi = bzr * czi + bzi * czr;
        float iur = fmaf(bzr, cur, fmaf(-bzi, cui, bur));
        float iui = fmaf(bzr, cui, fmaf(bzi, cur, bui));
        float* Ib = &g_aggI[((size_t)fidx * KD + k) * 4];
        Ib[0] = izr; Ib[1] = izi; Ib[2] = iur; Ib[3] = iui;
    }
    __syncthreads();
    if (tid == 0) {
        __threadfence();
        atomicExch(&g_flag[fidx], 2);
    }

    // ---------- phase 5: replay with carry, write output ----------
    float pzr = pre[(g * 64 + k) * 4 + 0];
    float pzi = pre[(g * 64 + k) * 4 + 1];
    float pur = pre[(g * 64 + k) * 4 + 2];
    float pui = pre[(g * 64 + k) * 4 + 3];
    float chr_ = carry[k];
    float chi  = carry[64 + k];
    float hr = fmaf(pzr, chr_, fmaf(-pzi, chi, pur));
    float hi = fmaf(pzr, chi, fmaf(pzi, chr_, pui));

    float* outp = out + base_bt * (2 * KD);
#pragma unroll 4
    for (int i = 0; i < GLEN; i++) {
        float rc, rs;
        zval(amp[(size_t)i * KD], omp_[(size_t)i * KD], tmp_[i], dtp[i], a0k, w0k, rc, rs);
        float u = fmaf(us[(g * GLEN + i) * KD + k], invs, bk);
        float hr2 = fmaf(rc, hr, fmaf(-rs, hi, u));
        float hi2 = fmaf(rc, hi, rs * hr);
        hr = hr2; hi = hi2;
        outp[(size_t)i * 128 + k]      = hr;
        outp[(size_t)i * 128 + 64 + k] = hi;
    }

    // ---------- cleanup: last block resets persistent state for next replay ----------
    __syncthreads();
    if (tid == 0) {
        __threadfence();
        int c = atomicAdd(&g_done, 1);
        ((int*)carry)[0] = (c == NBLK - 1) ? 1 : 0;
    }
    __syncthreads();
    if (((int*)carry)[0]) {
        g_flag[tid] = 0;
        if (tid == 0) {
            g_ready = 0;
            g_done = 0;
        }
    }
}

// ---------------- launch ----------------
extern "C" void kernel_launch(void* const* d_in, const int* in_sizes, int n_in,
                              void* d_out, int out_size) {
    const float* x      = (const float*)d_in[0];
    const float* dt     = (const float*)d_in[1];
    const float* amod   = (const float*)d_in[2];
    const float* omod   = (const float*)d_in[3];
    const float* tmod   = (const float*)d_in[4];
    const float* s_real = (const float*)d_in[5];
    const float* s_imag = (const float*)d_in[6];
    const float* tau_r  = (const float*)d_in[7];
    const float* W      = (const float*)d_in[8];
    const float* bvec   = (const float*)d_in[9];
    float* out = (float*)d_out;

    static const size_t main_smem =
        (CL * KD + 256 * 20 + 16 * 64 + NGROUP * KD * 4 * 2 + 2 * KD) * sizeof(float);

    cudaFuncSetAttribute(main_kernel, cudaFuncAttributeMaxDynamicSharedMemorySize, (int)main_smem);

    main_kernel<<<NBLK, NTHREADS, main_smem>>>(x, dt, amod, omod, tmod, out,
                                               W, bvec, s_real, s_imag, tau_r);
}